// round 14
// baseline (speedup 1.0000x reference)
#include <cuda_runtime.h>
#include <cuda_bf16.h>

#define NN 8192
#define DCAP 64u              // entries per node (P(deg>64) ~ 1e-15)
#define OVF_CAP (1u << 16)    // spill safety

// Static scratch. d_deg + counters reset by hc_finish each run.
// ELL packed 4-per-u64: entry j of node i lives at (j>>2)*4N + 4i + (j&3),
// so the finish reads uint2 (4 neighbors) per node per group, warp-coalesced
// (lanes t..t+31 -> 256B contiguous).
__device__ unsigned int d_deg[NN];                  // zero at load
__device__ unsigned short d_ell[DCAP * NN];         // 1MB
__device__ unsigned int d_ucount;                   // strictly-upper positives
__device__ unsigned int d_dcount;                   // diagonal positives
__device__ unsigned int d_ovfcnt;
__device__ unsigned int d_ovf[OVF_CAP];

__device__ __forceinline__ void scatter_dir(int node, int other) {
    unsigned j = atomicAdd(&d_deg[node], 1u);
    if (j < DCAP) {
        d_ell[(j >> 2) * (4u * NN) + ((unsigned)node << 2) + (j & 3u)] =
            (unsigned short)other;
    } else {
        unsigned o = atomicAdd(&d_ovfcnt, 1u);
        if (o < OVF_CAP) d_ovf[o] = ((unsigned)node << 13) | (unsigned)other;
    }
}

__device__ __forceinline__ void scatter_edge(int u, int v) {
    scatter_dir(u, v);
    scatter_dir(v, u);
}

// Upper-triangle scan, block per row pair (row, NN-1-row): NN+1 elements per
// block -> perfect balance. Hot loop (proven ~4.3 TB/s): 4 batched LDG.128,
// straight-line count, one uniform warp branch via ballot; hits scatter into
// the packed ELL (8192 distinct L2 atomic counters, hidden under the stream).
// Exactness: adj bitwise symmetric -> full positives = 2U + D; the
// reference's sum(adj>0)//2 = U + D//2 exactly.
__global__ void __launch_bounds__(256) hc_scan(const float* __restrict__ adj) {
    __shared__ unsigned s_cnt;
    const int t = threadIdx.x;
    const int pair = blockIdx.x;
    if (t == 0) s_cnt = 0u;
    __syncthreads();

    #pragma unroll
    for (int half = 0; half < 2; half++) {
        const int row = half ? (NN - 1 - pair) : pair;
        const float4* __restrict__ rowp = (const float4*)(adj + (size_t)row * NN);
        const int start4 = row >> 2;            // quad containing the diagonal

        if (t == 0) {
            // diagonal quad: cols may be <, ==, or > row
            float4 v = rowp[start4];
            int col0 = start4 << 2;
            float e[4] = {v.x, v.y, v.z, v.w};
            unsigned dd = 0, uu = 0;
            #pragma unroll
            for (int j = 0; j < 4; j++) {
                int col = col0 + j;
                if (e[j] > 0.0f) {
                    if (col == row) dd++;
                    else if (col > row) { uu++; scatter_edge(row, col); }
                }
            }
            if (dd) atomicAdd(&d_dcount, dd);
            if (uu) atomicAdd(&s_cnt, uu);
        }

        const int lim = NN / 4;
        for (int ib = start4 + 1; ib < lim; ib += 1024) {
            const float4 NEG = make_float4(-1.f, -1.f, -1.f, -1.f);
            const int i0 = ib + t;
            float4 v0 = NEG, v1 = NEG, v2 = NEG, v3 = NEG;
            if (i0       < lim) v0 = rowp[i0];
            if (i0 + 256 < lim) v1 = rowp[i0 + 256];
            if (i0 + 512 < lim) v2 = rowp[i0 + 512];
            if (i0 + 768 < lim) v3 = rowp[i0 + 768];

            unsigned k = (unsigned)(v0.x > 0.f) + (unsigned)(v0.y > 0.f)
                       + (unsigned)(v0.z > 0.f) + (unsigned)(v0.w > 0.f)
                       + (unsigned)(v1.x > 0.f) + (unsigned)(v1.y > 0.f)
                       + (unsigned)(v1.z > 0.f) + (unsigned)(v1.w > 0.f)
                       + (unsigned)(v2.x > 0.f) + (unsigned)(v2.y > 0.f)
                       + (unsigned)(v2.z > 0.f) + (unsigned)(v2.w > 0.f)
                       + (unsigned)(v3.x > 0.f) + (unsigned)(v3.y > 0.f)
                       + (unsigned)(v3.z > 0.f) + (unsigned)(v3.w > 0.f);

            if (__ballot_sync(0xFFFFFFFFu, k != 0u)) {
                if (k) {
                    atomicAdd(&s_cnt, k);
                    #pragma unroll
                    for (int q = 0; q < 4; q++) {
                        float4 v = (q == 0) ? v0 : (q == 1) ? v1 : (q == 2) ? v2 : v3;
                        int col0 = (i0 + q * 256) << 2;
                        float e[4] = {v.x, v.y, v.z, v.w};
                        #pragma unroll
                        for (int j = 0; j < 4; j++)
                            if (e[j] > 0.f) scatter_edge(row, col0 + j);
                    }
                }
            }
        }
    }

    __syncthreads();
    if (t == 0 && s_cnt) atomicAdd(&d_ucount, s_cnt);
}

// Single block, 1024 threads: pull min-label CC over the packed ELL.
// Thread t owns nodes {t, t+1024, ...} and is the ONLY writer of their
// labels (plain STS, zero atomics, monotone -> races benign). Per group
// step, all 8 owned nodes issue independent LDG.64 (4 neighbors each) ->
// 8-deep MLP; rows are pre-padded to group boundaries with self-ids so the
// extraction is branch-free. Fixpoint (no change in a pass, both edge
// directions present) => labels constant per component => lab[i]==i exactly
// at each component's min node.
__global__ void __launch_bounds__(1024) hc_finish(float* __restrict__ out) {
    __shared__ int lab[NN];                  // 32KB
    __shared__ int sh[1024];
    const int t = threadIdx.x;

    int gcnt[8];
    int gmax = 0;
    #pragma unroll
    for (int k = 0; k < 8; k++) {
        int i = t + (k << 10);
        lab[i] = i;
        unsigned d = min(d_deg[i], DCAP);
        int g = (int)((d + 3u) >> 2);
        gcnt[k] = g;
        gmax = max(gmax, g);
        // pad row tail to the group boundary with self-ids (owner-only I/O;
        // re-written every replay so stale data is harmless)
        for (unsigned j = d; j < ((unsigned)g << 2); j++)
            d_ell[(j >> 2) * (4u * NN) + ((unsigned)i << 2) + (j & 3u)] =
                (unsigned short)i;
    }
    __syncthreads();

    const uint2* __restrict__ ep = (const uint2*)d_ell;  // ep[g*NN + i]... u64 view
    const unsigned novf = min(d_ovfcnt, OVF_CAP);

    for (int iter = 0; iter < 64; iter++) {
        int changed = 0;
        int m[8];
        #pragma unroll
        for (int k = 0; k < 8; k++) m[k] = lab[t + (k << 10)];

        for (int g = 0; g < gmax; g++) {
            uint2 q[8];
            // batch up to 8 independent LDG.64 (predicated per node)
            #pragma unroll
            for (int k = 0; k < 8; k++)
                if (g < gcnt[k])
                    q[k] = ep[(unsigned)g * NN + (unsigned)(t + (k << 10))];
            #pragma unroll
            for (int k = 0; k < 8; k++) {
                if (g < gcnt[k]) {
                    int n0 = (int)(q[k].x & 0xFFFFu), n1 = (int)(q[k].x >> 16);
                    int n2 = (int)(q[k].y & 0xFFFFu), n3 = (int)(q[k].y >> 16);
                    if (iter == 0) {
                        // labels are identity on pass 1: min over ids directly
                        m[k] = min(m[k], min(min(n0, n1), min(n2, n3)));
                    } else {
                        int v0 = lab[n0], v1 = lab[n1];
                        int v2 = lab[n2], v3 = lab[n3];
                        m[k] = min(m[k], min(min(v0, v1), min(v2, v3)));
                    }
                }
            }
        }

        #pragma unroll
        for (int k = 0; k < 8; k++) {
            int i = t + (k << 10);
            if (m[k] < lab[i]) { lab[i] = m[k]; changed = 1; }  // owner-only
        }

        // overflow spill (expected empty; atomics OK here)
        for (unsigned idx = t; idx < novf; idx += 1024) {
            unsigned e = d_ovf[idx];
            int u = (int)(e >> 13), v = (int)(e & 8191u);
            int lu = lab[u], lv = lab[v];
            if (lu != lv) {
                changed = 1;
                if (lu < lv) atomicMin(&lab[v], lu);
                else         atomicMin(&lab[u], lv);
            }
        }

        int any = __syncthreads_or(changed);

        // pointer jump x2 (owner-only, monotone: lab[l] <= l)
        #pragma unroll
        for (int r = 0; r < 2; r++) {
            #pragma unroll
            for (int k = 0; k < 8; k++) {
                int i = t + (k << 10);
                int l = lab[i];
                int ll = lab[l];
                if (ll < l) lab[i] = ll;
            }
            __syncthreads();
        }
        if (!any) break;
    }

    int roots = 0;
    #pragma unroll
    for (int k = 0; k < 8; k++) {
        int i = t + (k << 10);
        roots += (lab[i] == i) ? 1 : 0;
    }
    sh[t] = roots;
    __syncthreads();
    for (int s = 512; s > 0; s >>= 1) {
        if (t < s) sh[t] += sh[t + s];
        __syncthreads();
    }
    if (t == 0) {
        float n_comp  = (float)sh[0];
        unsigned half_edges = d_ucount + (d_dcount >> 1);   // (2U+D)//2
        float n_edges = (float)half_edges;
        float betti1  = n_edges - (float)NN + n_comp;
        float n_cyc   = fmaxf(0.0f, betti1);
        float comp_l  = (n_comp - 1.0f) * (n_comp - 1.0f);
        out[0] = comp_l + n_cyc * n_cyc;
    }
    // reset state for the next replay
    #pragma unroll
    for (int k = 0; k < 8; k++)
        d_deg[t + (k << 10)] = 0u;
    if (t == 0) { d_ucount = 0u; d_dcount = 0u; d_ovfcnt = 0u; }
}

extern "C" void kernel_launch(void* const* d_in, const int* in_sizes, int n_in,
                              void* d_out, int out_size) {
    const float* adj = (const float*)d_in[0];
    float* out = (float*)d_out;

    hc_scan<<<NN / 2, 256>>>(adj);
    hc_finish<<<1, 1024>>>(out);
}

// round 15
// speedup vs baseline: 1.9238x; 1.9238x over previous
#include <cuda_runtime.h>
#include <cuda_bf16.h>

#define NN 8192
#define ECAP (1u << 20)    // 1M compacted edge slots (4MB) — ~13x over ~78k
#define BUFCAP 4096u       // per-block smem staging (16KB)
#define OVF_CAP (1u << 16) // spill safety
#define FB 64              // finish blocks (all co-resident on 148 SMs)
#define FT 128             // finish threads/block; FB*FT == NN

// Static scratch. Counters reset by hc_finish each run.
__device__ unsigned int d_necnt;        // compacted edges
__device__ unsigned int d_dcount;       // diagonal positives
__device__ unsigned int d_edges[ECAP];  // (row<<13)|col
__device__ unsigned int d_ovfcnt;
__device__ unsigned int d_ovf[OVF_CAP];
__device__ int d_lab[NN];
__device__ unsigned int d_roots;
__device__ unsigned int d_chg[64];      // per-pass convergence flags (zeroed each run)
__device__ unsigned int d_bar_cnt;      // grid barrier state
__device__ unsigned int d_bar_gen;      // monotone generation (never reset)

// Upper-triangle scan, block per row pair (row, NN-1-row): NN+1 elements per
// block -> perfect balance. Hot loop (proven ~4.3 TB/s): 4 batched LDG.128,
// straight-line count, one uniform warp branch via ballot; hits append to a
// SMEM staging buffer. Block end: ONE global atomicAdd reserves a range in
// the compacted list + coalesced copy-out.
// Exactness: adj bitwise symmetric -> full positives = 2U + D; the
// reference's sum(adj>0)//2 = U + D//2 exactly.
__global__ void __launch_bounds__(256) hc_scan(const float* __restrict__ adj) {
    __shared__ unsigned s_cnt;
    __shared__ unsigned s_base;
    __shared__ unsigned s_buf[BUFCAP];
    const int t = threadIdx.x;
    const int pair = blockIdx.x;
    if (t == 0) s_cnt = 0u;
    __syncthreads();

    #pragma unroll
    for (int half = 0; half < 2; half++) {
        const int row = half ? (NN - 1 - pair) : pair;
        const float4* __restrict__ rowp = (const float4*)(adj + (size_t)row * NN);
        const int start4 = row >> 2;            // quad containing the diagonal
        const unsigned enc_row = (unsigned)row << 13;

        if (t == 0) {
            // diagonal quad: cols may be <, ==, or > row
            float4 v = rowp[start4];
            int col0 = start4 << 2;
            float e[4] = {v.x, v.y, v.z, v.w};
            unsigned dd = 0;
            #pragma unroll
            for (int j = 0; j < 4; j++) {
                int col = col0 + j;
                if (e[j] > 0.0f) {
                    if (col == row) dd++;
                    else if (col > row) {
                        unsigned b = atomicAdd(&s_cnt, 1u);
                        if (b < BUFCAP) s_buf[b] = enc_row | (unsigned)col;
                        else {
                            unsigned o = atomicAdd(&d_ovfcnt, 1u);
                            if (o < OVF_CAP) d_ovf[o] = enc_row | (unsigned)col;
                        }
                    }
                }
            }
            if (dd) atomicAdd(&d_dcount, dd);
        }

        const int lim = NN / 4;
        for (int ib = start4 + 1; ib < lim; ib += 1024) {
            const float4 NEG = make_float4(-1.f, -1.f, -1.f, -1.f);
            const int i0 = ib + t;
            float4 v0 = NEG, v1 = NEG, v2 = NEG, v3 = NEG;
            if (i0       < lim) v0 = rowp[i0];
            if (i0 + 256 < lim) v1 = rowp[i0 + 256];
            if (i0 + 512 < lim) v2 = rowp[i0 + 512];
            if (i0 + 768 < lim) v3 = rowp[i0 + 768];

            unsigned k = (unsigned)(v0.x > 0.f) + (unsigned)(v0.y > 0.f)
                       + (unsigned)(v0.z > 0.f) + (unsigned)(v0.w > 0.f)
                       + (unsigned)(v1.x > 0.f) + (unsigned)(v1.y > 0.f)
                       + (unsigned)(v1.z > 0.f) + (unsigned)(v1.w > 0.f)
                       + (unsigned)(v2.x > 0.f) + (unsigned)(v2.y > 0.f)
                       + (unsigned)(v2.z > 0.f) + (unsigned)(v2.w > 0.f)
                       + (unsigned)(v3.x > 0.f) + (unsigned)(v3.y > 0.f)
                       + (unsigned)(v3.z > 0.f) + (unsigned)(v3.w > 0.f);

            if (__ballot_sync(0xFFFFFFFFu, k != 0u)) {
                if (k) {
                    unsigned idx = atomicAdd(&s_cnt, k);
                    #pragma unroll
                    for (int q = 0; q < 4; q++) {
                        float4 v = (q == 0) ? v0 : (q == 1) ? v1 : (q == 2) ? v2 : v3;
                        int col0 = (i0 + q * 256) << 2;
                        float e[4] = {v.x, v.y, v.z, v.w};
                        #pragma unroll
                        for (int j = 0; j < 4; j++) {
                            if (e[j] > 0.f) {
                                if (idx < BUFCAP)
                                    s_buf[idx] = enc_row | (unsigned)(col0 + j);
                                else {
                                    unsigned o = atomicAdd(&d_ovfcnt, 1u);
                                    if (o < OVF_CAP) d_ovf[o] = enc_row | (unsigned)(col0 + j);
                                }
                                idx++;
                            }
                        }
                    }
                }
            }
        }
    }

    // compact: one global atomic per block, then coalesced copy-out
    __syncthreads();
    if (t == 0) {
        unsigned c = min(s_cnt, BUFCAP);
        s_base = atomicAdd(&d_necnt, c);
    }
    __syncthreads();
    unsigned c = min(s_cnt, BUFCAP);
    unsigned base = s_base;
    for (unsigned i = t; i < c; i += 256)
        if (base + i < ECAP) d_edges[base + i] = s_buf[i];
}

// Software grid barrier: sense-reversing on a monotone generation counter.
// FB=64 blocks always co-resident on 148 SMs -> deadlock-free.
__device__ __forceinline__ void grid_barrier() {
    __syncthreads();
    if (threadIdx.x == 0) {
        unsigned my = *(volatile unsigned*)&d_bar_gen;
        __threadfence();
        if (atomicAdd(&d_bar_cnt, 1u) == FB - 1u) {
            d_bar_cnt = 0u;
            __threadfence();
            atomicExch(&d_bar_gen, my + 1u);
        } else {
            while (*(volatile unsigned*)&d_bar_gen == my) { }
        }
        __threadfence();
    }
    __syncthreads();
}

// Distributed min-label CC: 8192 threads across 64 SMs, 1 node each.
// Per pass: stream the compacted edge list (coalesced uint4, ~2.4 groups per
// thread), push atomicMin to both endpoints only when labels differ
// (monotone -> stale reads benign; fire-and-forget), pointer-jump own node,
// per-pass convergence flag. A pass where every edge saw equal labels =>
// labels constant per component => lab[i]==i exactly at component minima.
__global__ void __launch_bounds__(FT) hc_finish(float* __restrict__ out) {
    const int g = blockIdx.x * FT + threadIdx.x;   // node id, 0..NN-1

    d_lab[g] = g;
    grid_barrier();

    const unsigned n = min(d_necnt, ECAP);
    const unsigned novf = min(d_ovfcnt, OVF_CAP);
    const unsigned n4 = n >> 2;
    const uint4* e4p = (const uint4*)d_edges;

    for (int pass = 0; pass < 64; pass++) {
        int changed = 0;

        for (unsigned i = g; i < n4; i += (unsigned)(FB * FT)) {
            uint4 q = e4p[i];
            unsigned w[4] = {q.x, q.y, q.z, q.w};
            #pragma unroll
            for (int h = 0; h < 4; h++) {
                int u = (int)(w[h] >> 13), v = (int)(w[h] & 8191u);
                int lu = d_lab[u], lv = d_lab[v];
                if (lu != lv) {
                    changed = 1;
                    int mn = min(lu, lv);
                    if (lv != mn) atomicMin(&d_lab[v], mn);
                    else          atomicMin(&d_lab[u], mn);
                }
            }
        }
        for (unsigned i = (n4 << 2) + (unsigned)g; i < n; i += (unsigned)(FB * FT)) {
            unsigned e = d_edges[i];
            int u = (int)(e >> 13), v = (int)(e & 8191u);
            int lu = d_lab[u], lv = d_lab[v];
            if (lu != lv) {
                changed = 1;
                int mn = min(lu, lv);
                if (lv != mn) atomicMin(&d_lab[v], mn);
                else          atomicMin(&d_lab[u], mn);
            }
        }
        for (unsigned i = (unsigned)g; i < novf; i += (unsigned)(FB * FT)) {
            unsigned e = d_ovf[i];
            int u = (int)(e >> 13), v = (int)(e & 8191u);
            int lu = d_lab[u], lv = d_lab[v];
            if (lu != lv) {
                changed = 1;
                int mn = min(lu, lv);
                atomicMin(&d_lab[v], mn);
                atomicMin(&d_lab[u], mn);
            }
        }

        // pointer jump own node (monotone; concurrent mins benign)
        int l = d_lab[g];
        int ll = d_lab[l];
        if (ll < l) atomicMin(&d_lab[g], ll);

        int any = __syncthreads_or(changed);
        if (threadIdx.x == 0 && any) atomicOr(&d_chg[pass], 1u);
        grid_barrier();
        if (d_chg[pass] == 0u) break;
    }

    // count roots: lab[i]==i exactly at each component's min node
    int root = (d_lab[g] == g) ? 1 : 0;
    int bsum = __syncthreads_count(root);
    if (threadIdx.x == 0) atomicAdd(&d_roots, (unsigned)bsum);
    grid_barrier();

    if (g == 0) {
        float n_comp  = (float)d_roots;
        unsigned U = d_necnt + d_ovfcnt;                // exact upper positives
        unsigned half_edges = U + (d_dcount >> 1);      // (2U+D)//2
        float n_edges = (float)half_edges;
        float betti1  = n_edges - (float)NN + n_comp;
        float n_cyc   = fmaxf(0.0f, betti1);
        float comp_l  = (n_comp - 1.0f) * (n_comp - 1.0f);
        out[0] = comp_l + n_cyc * n_cyc;
        // reset for the next replay
        d_necnt = 0u; d_dcount = 0u; d_ovfcnt = 0u; d_roots = 0u;
    }
    if (g < 64) d_chg[g] = 0u;
}

extern "C" void kernel_launch(void* const* d_in, const int* in_sizes, int n_in,
                              void* d_out, int out_size) {
    const float* adj = (const float*)d_in[0];
    float* out = (float*)d_out;

    hc_scan<<<NN / 2, 256>>>(adj);
    hc_finish<<<FB, FT>>>(out);
}